// round 15
// baseline (speedup 1.0000x reference)
#include <cuda_runtime.h>
#include <cuda_fp16.h>

#define N0V   8192
#define N1V   100000
#define N2V   300000
#define KNBR  32
#define DD    64

#define NCHUNK 4
#define CH     (N1V / NCHUNK)      // 25000 rows per hop-1 chunk

typedef unsigned long long u64t;

#define PACKU64(out, lo, hi)  asm("mov.b64 %0, {%1, %2};" : "=l"(out) : "f"(lo), "f"(hi))
#define SPLATF64(out, v)      asm("mov.b64 %0, {%1, %1};" : "=l"(out) : "f"(v))
#define UNPACKF64(lo, hi, in) asm("mov.b64 {%0, %1}, %2;" : "=f"(lo), "=f"(hi) : "l"(in))
#define FFMA2(acc, a, b)      asm("fma.rn.f32x2 %0, %1, %2, %0;" : "+l"(acc) : "l"(a), "l"(b))

// Scratch (device globals — allocation in kernel_launch is forbidden).
__device__ __half g_v2h[(size_t)N2V * DD];    // 38.4 MB gather target
__device__ __half g_agg1[(size_t)N1V * DD];   // 12.8 MB hop-1 aggregates
__device__ __half g_h1h[(size_t)N1V * DD];    // 12.8 MB hop-1 activations
__device__ __half g_agg0[(size_t)N0V * DD];   // 1 MB   seed aggregates

// ---------------------------------------------------------------------------
// K1: v2h = half(feats[node_ids2]); 4 rows per thread.
// ---------------------------------------------------------------------------
__global__ void gather_v2h_kernel(const float* __restrict__ feats,
                                  const int*   __restrict__ node_ids2)
{
    int t = blockIdx.x * blockDim.x + threadIdx.x;
    const int Q = N2V / 4;
    const int quarter_total = Q * (DD / 4);
    if (t >= quarter_total) return;
    int row = t >> 4;
    int c   = t & 15;

    int src[4];
    #pragma unroll
    for (int q = 0; q < 4; ++q)
        src[q] = __ldg(node_ids2 + row + q * Q);

    float4 v[4];
    #pragma unroll
    for (int q = 0; q < 4; ++q)
        v[q] = __ldg((const float4*)(feats + (size_t)src[q] * DD) + c);

    #pragma unroll
    for (int q = 0; q < 4; ++q) {
        __half2 h0 = __floats2half2_rn(v[q].x, v[q].y);
        __half2 h1 = __floats2half2_rn(v[q].z, v[q].w);
        uint2 p;
        p.x = *(unsigned int*)&h0;
        p.y = *(unsigned int*)&h1;
        ((uint2*)g_v2h)[(size_t)(row + q * Q) * 16 + c] = p;
    }
}

// ---------------------------------------------------------------------------
// Gather-mean, 1 row/warp. SYNC: PDL grid-dependency sync before touching
// predecessor output (only needed for PDL-attributed launches).
// ---------------------------------------------------------------------------
template<bool SYNC>
__global__ void __launch_bounds__(256) agg_mean1_kernel(
    const uint4* __restrict__ vsrc,
    const int*   __restrict__ nbr,
    __half*      __restrict__ aggout,
    int nrows)
{
    const int tid  = threadIdx.x;
    const int lane = tid & 31;
    const int warp = tid >> 5;
    const int row  = blockIdx.x * 8 + warp;
    const int cr   = min(row, nrows - 1);

    const int idx = __ldg(nbr + (size_t)cr * KNBR + lane);  // independent input

    if (SYNC) cudaGridDependencySynchronize();

    if (row >= nrows) return;
    const int sub = lane >> 3;
    const int ch  = lane & 7;

    __half2 zero = __float2half2_rn(0.f);
    __half2 acc[2][4];
    #pragma unroll
    for (int s = 0; s < 2; ++s)
        #pragma unroll
        for (int j = 0; j < 4; ++j) acc[s][j] = zero;

    #pragma unroll
    for (int i = 0; i < 8; ++i) {
        int n = __shfl_sync(0xffffffffu, idx, 4 * i + sub);
        uint4 d = __ldg(vsrc + (size_t)n * 8 + ch);
        const __half2* h = (const __half2*)&d;
        int s = i & 1;
        #pragma unroll
        for (int j = 0; j < 4; ++j)
            acc[s][j] = __hadd2(acc[s][j], h[j]);
    }

    float f[8];
    #pragma unroll
    for (int j = 0; j < 4; ++j) {
        float2 v = __half22float2(__hadd2(acc[0][j], acc[1][j]));
        f[2 * j] = v.x;  f[2 * j + 1] = v.y;
    }
    #pragma unroll
    for (int d = 8; d <= 16; d <<= 1)
        #pragma unroll
        for (int j = 0; j < 8; ++j)
            f[j] += __shfl_xor_sync(0xffffffffu, f[j], d);

    const float inv = 1.0f / KNBR;
    if (sub == 0) {
        __half2 h[4];
        #pragma unroll
        for (int j = 0; j < 4; ++j)
            h[j] = __floats2half2_rn(f[2 * j] * inv, f[2 * j + 1] * inv);
        ((uint4*)aggout)[(size_t)row * 8 + ch] = *(uint4*)h;
    }
}

// ---------------------------------------------------------------------------
// FFMA GEMM: out = relu(A @ W + b), A fp16 [nrows,64].
// ---------------------------------------------------------------------------
#define SA_STRIDE 68

template<bool HALF_OUT, bool SYNC>
__global__ void __launch_bounds__(256) gemm64_kernel(
    const __half* __restrict__ A,
    const float*  __restrict__ W,
    const float*  __restrict__ bias,
    void*         __restrict__ out,
    int nrows)
{
    __shared__ float  sW[DD * DD];
    __shared__ __half sA[128 * SA_STRIDE];

    const int tid = threadIdx.x;

    #pragma unroll
    for (int i = tid; i < DD * DD / 4; i += 256)
        ((float4*)sW)[i] = __ldg((const float4*)W + i);

    const int rp   = tid >> 3;
    const int col0 = (tid & 7) * 8;
    float4 bv0 = __ldg((const float4*)(bias + col0));
    float4 bv1 = __ldg((const float4*)(bias + col0 + 4));

    if (SYNC) cudaGridDependencySynchronize();

    const int rowbase = blockIdx.x * 128;
    for (int i = tid; i < 2048; i += 256) {
        int r = i >> 4, c = i & 15;
        int gr = min(rowbase + r, nrows - 1);
        uint2 v = __ldg((const uint2*)(A + (size_t)gr * DD) + c);
        *(uint2*)&sA[r * SA_STRIDE + c * 4] = v;
    }
    __syncthreads();

    u64t bp[4];
    PACKU64(bp[0], bv0.x, bv0.y);  PACKU64(bp[1], bv0.z, bv0.w);
    PACKU64(bp[2], bv1.x, bv1.y);  PACKU64(bp[3], bv1.z, bv1.w);
    u64t acc[4][4];
    #pragma unroll
    for (int r = 0; r < 4; ++r)
        #pragma unroll
        for (int j = 0; j < 4; ++j) acc[r][j] = bp[j];

    #pragma unroll
    for (int k = 0; k < DD; k += 2) {
        ulonglong2 wA01 = *(const ulonglong2*)&sW[k * DD + col0];
        ulonglong2 wA23 = *(const ulonglong2*)&sW[k * DD + col0 + 4];
        ulonglong2 wB01 = *(const ulonglong2*)&sW[(k + 1) * DD + col0];
        ulonglong2 wB23 = *(const ulonglong2*)&sW[(k + 1) * DD + col0 + 4];
        #pragma unroll
        for (int r = 0; r < 4; ++r) {
            __half2 ah = *(const __half2*)&sA[(4 * rp + r) * SA_STRIDE + k];
            float2 af = __half22float2(ah);
            u64t s0, s1;
            SPLATF64(s0, af.x);
            SPLATF64(s1, af.y);
            FFMA2(acc[r][0], s0, wA01.x);  FFMA2(acc[r][1], s0, wA01.y);
            FFMA2(acc[r][2], s0, wA23.x);  FFMA2(acc[r][3], s0, wA23.y);
            FFMA2(acc[r][0], s1, wB01.x);  FFMA2(acc[r][1], s1, wB01.y);
            FFMA2(acc[r][2], s1, wB23.x);  FFMA2(acc[r][3], s1, wB23.y);
        }
    }

    #pragma unroll
    for (int r = 0; r < 4; ++r) {
        int grow = rowbase + 4 * rp + r;
        if (grow >= nrows) continue;
        if (HALF_OUT) {
            __half2 h[4];
            #pragma unroll
            for (int j = 0; j < 4; ++j) {
                float lo, hi;
                UNPACKF64(lo, hi, acc[r][j]);
                h[j] = __floats2half2_rn(fmaxf(lo, 0.f), fmaxf(hi, 0.f));
            }
            *(uint4*)((__half*)out + (size_t)grow * DD + col0) = *(uint4*)h;
        } else {
            float* op = (float*)out + (size_t)grow * DD + col0;
            #pragma unroll
            for (int j = 0; j < 4; ++j) {
                float lo, hi;
                UNPACKF64(lo, hi, acc[r][j]);
                op[2 * j]     = fmaxf(lo, 0.f);
                op[2 * j + 1] = fmaxf(hi, 0.f);
            }
        }
    }
}

// ---------------------------------------------------------------------------
// PDL launch helper (stream 0).
// ---------------------------------------------------------------------------
template<typename... Args>
static void launch_pdl(void (*kern)(Args...), dim3 grid, dim3 block, Args... args)
{
    cudaLaunchConfig_t cfg = {};
    cfg.gridDim  = grid;
    cfg.blockDim = block;
    cfg.stream   = 0;
    cudaLaunchAttribute attr[1];
    attr[0].id = cudaLaunchAttributeProgrammaticStreamSerialization;
    attr[0].val.programmaticStreamSerializationAllowed = 1;
    cfg.attrs = attr;
    cfg.numAttrs = 1;
    cudaLaunchKernelEx(&cfg, kern, args...);
}

// One-time stream/event creation (not device memory; created on the
// non-captured correctness call, reused identically on every call).
static cudaStream_t g_s1 = 0;
static cudaEvent_t  g_eA[NCHUNK];
static cudaEvent_t  g_eG;
static void ensure_streams()
{
    if (!g_s1) {
        cudaStreamCreateWithFlags(&g_s1, cudaStreamNonBlocking);
        for (int i = 0; i < NCHUNK; ++i)
            cudaEventCreateWithFlags(&g_eA[i], cudaEventDisableTiming);
        cudaEventCreateWithFlags(&g_eG, cudaEventDisableTiming);
    }
}

// ---------------------------------------------------------------------------
// Inputs: 0 feats, 1 W0, 2 b0, 3 W1, 4 b1, 5 neigh_idx0, 6 neigh_idx1,
//         7 node_ids1 (unused), 8 node_ids2
// Pipeline: agg chunks (mem-bound) in stream 0 overlap gemm chunks
// (fma-bound) in side stream; fork/join via events (graph-capture pattern).
// ---------------------------------------------------------------------------
extern "C" void kernel_launch(void* const* d_in, const int* in_sizes, int n_in,
                              void* d_out, int out_size)
{
    const float* feats      = (const float*)d_in[0];
    const float* W0         = (const float*)d_in[1];
    const float* b0         = (const float*)d_in[2];
    const float* W1         = (const float*)d_in[3];
    const float* b1         = (const float*)d_in[4];
    const int*   neigh_idx0 = (const int*)  d_in[5];
    const int*   neigh_idx1 = (const int*)  d_in[6];
    const int*   node_ids2  = (const int*)  d_in[8];
    float*       out        = (float*)d_out;

    __half* v2h;  cudaGetSymbolAddress((void**)&v2h,  g_v2h);
    __half* agg1; cudaGetSymbolAddress((void**)&agg1, g_agg1);
    __half* h1h;  cudaGetSymbolAddress((void**)&h1h,  g_h1h);
    __half* agg0; cudaGetSymbolAddress((void**)&agg0, g_agg0);

    ensure_streams();

    // K1 (stream 0).
    {
        const int quarter_total = (N2V / 4) * (DD / 4);
        gather_v2h_kernel<<<(quarter_total + 255) / 256, 256>>>(feats, node_ids2);
    }

    // Hop-1 agg chunks in stream 0; chunk 0 PDL-overlaps K1's tail.
    launch_pdl(agg_mean1_kernel<true>, dim3(CH / 8), dim3(256),
               (const uint4*)v2h, neigh_idx1, agg1, (int)CH);
    cudaEventRecord(g_eA[0], 0);
    for (int c = 1; c < NCHUNK; ++c) {
        agg_mean1_kernel<false><<<CH / 8, 256>>>(
            (const uint4*)v2h,
            neigh_idx1 + (size_t)c * CH * KNBR,
            agg1 + (size_t)c * CH * DD, (int)CH);
        cudaEventRecord(g_eA[c], 0);
    }

    // Hop-1 gemm chunks in side stream, each after its agg chunk;
    // gemm_c runs concurrently with agg_{c+1}.
    for (int c = 0; c < NCHUNK; ++c) {
        cudaStreamWaitEvent(g_s1, g_eA[c], 0);
        gemm64_kernel<true, false><<<(CH + 127) / 128, 256, 0, g_s1>>>(
            agg1 + (size_t)c * CH * DD, W0, b0,
            (void*)(h1h + (size_t)c * CH * DD), (int)CH);
    }
    cudaEventRecord(g_eG, g_s1);

    // Join: seed layer needs all gemm chunks.
    cudaStreamWaitEvent(0, g_eG, 0);
    agg_mean1_kernel<false><<<N0V / 8, 256>>>(
        (const uint4*)h1h, neigh_idx0, agg0, N0V);
    launch_pdl(gemm64_kernel<false, true>, dim3(N0V / 128), dim3(256),
               (const __half*)agg0, W1, b1, (void*)out, (int)N0V);
}